// round 15
// baseline (speedup 1.0000x reference)
#include <cuda_runtime.h>

#define NMAX   200000
#define HDIM   64
#define CDIM   128
#define KEEPK  63
#define KCONV  62   // offsets handled by kb (center k=62 fused into k1)

// ---- device scratch (static; no allocation) ------------------------------
__device__ __align__(16) float g_f  [(size_t)NMAX * HDIM];   // 51.2 MB
__device__ __align__(16) float g_acc[(size_t)NMAX * HDIM];   // 51.2 MB
__device__ __align__(16) float g_Wbr[(size_t)KCONV * 4096];  // 1 MB repacked Wb
__device__ int2  g_pairs[(size_t)KCONV * NMAX];              // 99.2 MB
__device__ int   g_cnt[KEEPK];

typedef unsigned long long u64;

__device__ __forceinline__ void ffma2(u64 &acc, u64 a, u64 b) {
    asm("fma.rn.f32x2 %0, %1, %2, %0;" : "+l"(acc) : "l"(a), "l"(b));
}
__device__ __forceinline__ float pairsum(u64 v) {
    return __uint_as_float((unsigned)v) + __uint_as_float((unsigned)(v >> 32));
}
__device__ __forceinline__ float eluf(float v) {
    return v > 0.f ? v : __expf(v) - 1.f;
}
__device__ __forceinline__ void red_add_v4(float* p, float a, float b, float c, float d) {
    asm volatile("red.global.add.v4.f32 [%0], {%1, %2, %3, %4};"
                 :: "l"(p), "f"(a), "f"(b), "f"(c), "f"(d) : "memory");
}
__device__ __forceinline__ void cp16(unsigned dst, const void* src, int szbytes) {
    asm volatile("cp.async.cg.shared.global [%0], [%1], 16, %2;"
                 :: "r"(dst), "l"(src), "r"(szbytes) : "memory");
}
__device__ __forceinline__ void cp_commit() {
    asm volatile("cp.async.commit_group;" ::: "memory");
}
__device__ __forceinline__ void cp_wait0() {
    asm volatile("cp.async.wait_group 0;" ::: "memory");
}

// ---------------------------------------------------------------------------
// kZ: zero counters + pre-repack all Wb[k], k<62, into g_Wbr (kb's layout).
// ---------------------------------------------------------------------------
__global__ void kz_kernel(const float* __restrict__ Wb)
{
    int k = blockIdx.x;
    int tid = threadIdx.x;
    if (k == 0 && tid < KEEPK) g_cnt[tid] = 0;
    float* dst = &g_Wbr[(size_t)k * 4096];
    for (int j = tid; j < 1024; j += 256) {
        int dd = j >> 4, c0 = (j & 15) * 4;
        float4 w = *(const float4*)&Wb[(size_t)k * 4096 + dd * 64 + c0];
        int basew = (dd >> 1) * 128 + (c0 >> 2) * 4 + (dd & 1);
        dst[basew + 0]  = w.x;
        dst[basew + 2]  = w.y;
        dst[basew + 64] = w.z;
        dst[basew + 66] = w.w;
    }
}

// ---------------------------------------------------------------------------
// kA: compaction over a half-range [k0, k0+31). 512 threads; block-aggregated
// atomics: ONE atomicAdd per block.
// ---------------------------------------------------------------------------
__global__ void ka_kernel(const int* __restrict__ nidx, int N, int k0)
{
    __shared__ int wcnt[16];
    __shared__ int sbase;
    int k = k0 + blockIdx.y;
    int r = blockIdx.x * blockDim.x + threadIdx.x;
    int idx = -1;
    if (r < N) idx = nidx[(size_t)k * N + r];
    bool valid = idx >= 0;
    unsigned m = __ballot_sync(0xffffffffu, valid);
    int wid = threadIdx.x >> 5, lane = threadIdx.x & 31;
    if (lane == 0) wcnt[wid] = __popc(m);
    __syncthreads();
    if (threadIdx.x == 0) {
        int s = 0;
        #pragma unroll
        for (int w = 0; w < 16; w++) { int c = wcnt[w]; wcnt[w] = s; s += c; }
        sbase = s ? atomicAdd(&g_cnt[k], s) : 0;
    }
    __syncthreads();
    if (valid) {
        int pos = sbase + wcnt[wid] + __popc(m & ((1u << lane) - 1));
        g_pairs[(size_t)k * NMAX + pos] = make_int2(r, idx);
    }
}

// ---------------------------------------------------------------------------
// k1: f = elu( elu(x+y) @ Wa );  g_f = f;  g_acc = f @ Wb[62]  (center fused)
// ---------------------------------------------------------------------------
#define SA_STRIDE 132
#define FB_STRIDE 68

__global__ __launch_bounds__(256, 3)
void k1_kernel(const float* __restrict__ x, const float* __restrict__ y,
               const float* __restrict__ Wa, const float* __restrict__ Wb,
               int N)
{
    extern __shared__ float sm[];
    float* sWa = sm;            // 8192 (pair-major Wa; later reused for Wb62)
    float* sA  = sm + 8192;     // 64*132 = 8448 (input tile; later f tile)

    int tid = threadIdx.x;
    int r0  = blockIdx.x * 64;

    for (int j = tid; j < 2048; j += 256) {
        int d = j >> 4, c0 = (j & 15) * 4;
        float4 w = *(const float4*)&Wa[d * 64 + c0];
        int base = (d >> 1) * 128 + (d & 1);
        sWa[base + 2 * (c0 + 0)] = w.x;
        sWa[base + 2 * (c0 + 1)] = w.y;
        sWa[base + 2 * (c0 + 2)] = w.z;
        sWa[base + 2 * (c0 + 3)] = w.w;
    }
    for (int j = tid; j < 2048; j += 256) {
        int r = j >> 5, c0 = (j & 31) * 4;
        int gr = r0 + r;
        float4 v = make_float4(0.f, 0.f, 0.f, 0.f);
        if (gr < N) {
            float4 xv = *(const float4*)&x[(size_t)gr * CDIM + c0];
            float4 yv = *(const float4*)&y[(size_t)gr * CDIM + c0];
            v.x = eluf(xv.x + yv.x); v.y = eluf(xv.y + yv.y);
            v.z = eluf(xv.z + yv.z); v.w = eluf(xv.w + yv.w);
        }
        *(float4*)&sA[r * SA_STRIDE + c0] = v;
    }
    __syncthreads();

    int wid = tid >> 5, lane = tid & 31;
    int cg = lane & 15, rg = lane >> 4;
    int rbase = wid * 8 + rg * 4;

    u64 acc[4][4];
    #pragma unroll
    for (int i = 0; i < 4; i++)
        #pragma unroll
        for (int j = 0; j < 4; j++) acc[i][j] = 0ull;

    #pragma unroll 2
    for (int dp2 = 0; dp2 < 32; dp2++) {
        ulonglong2 a2[4];
        #pragma unroll
        for (int i = 0; i < 4; i++)
            a2[i] = *(const ulonglong2*)&sA[(rbase + i) * SA_STRIDE + 4 * dp2];
        ulonglong2 wA0 = *(const ulonglong2*)&sWa[(2 * dp2) * 128 + 4 * cg];
        ulonglong2 wA1 = *(const ulonglong2*)&sWa[(2 * dp2) * 128 + 64 + 4 * cg];
        ulonglong2 wB0 = *(const ulonglong2*)&sWa[(2 * dp2 + 1) * 128 + 4 * cg];
        ulonglong2 wB1 = *(const ulonglong2*)&sWa[(2 * dp2 + 1) * 128 + 64 + 4 * cg];
        #pragma unroll
        for (int i = 0; i < 4; i++) {
            ffma2(acc[i][0], a2[i].x, wA0.x);
            ffma2(acc[i][1], a2[i].x, wA0.y);
            ffma2(acc[i][2], a2[i].x, wA1.x);
            ffma2(acc[i][3], a2[i].x, wA1.y);
            ffma2(acc[i][0], a2[i].y, wB0.x);
            ffma2(acc[i][1], a2[i].y, wB0.y);
            ffma2(acc[i][2], a2[i].y, wB1.x);
            ffma2(acc[i][3], a2[i].y, wB1.y);
        }
    }
    float2 f0[4], f1[4];
    #pragma unroll
    for (int i = 0; i < 4; i++) {
        f0[i].x = eluf(pairsum(acc[i][0]));
        f0[i].y = eluf(pairsum(acc[i][1]));
        f1[i].x = eluf(pairsum(acc[i][2]));
        f1[i].y = eluf(pairsum(acc[i][3]));
    }
    __syncthreads();   // all GEMM1 smem reads done; sA/sWa reusable

    #pragma unroll
    for (int i = 0; i < 4; i++) {
        int grow = r0 + rbase + i;
        *(float2*)&sA[(rbase + i) * FB_STRIDE + 2 * cg]      = f0[i];
        *(float2*)&sA[(rbase + i) * FB_STRIDE + 2 * cg + 32] = f1[i];
        if (grow < N) {
            *(float2*)&g_f[(size_t)grow * HDIM + 2 * cg]      = f0[i];
            *(float2*)&g_f[(size_t)grow * HDIM + 2 * cg + 32] = f1[i];
        }
    }
    for (int j = tid; j < 1024; j += 256) {
        int dd = j >> 4, c0 = (j & 15) * 4;
        float4 w = *(const float4*)&Wb[(size_t)KCONV * 4096 + dd * 64 + c0];
        int basew = (dd >> 1) * 128 + (c0 >> 2) * 4 + (dd & 1);
        sWa[basew + 0]  = w.x;
        sWa[basew + 2]  = w.y;
        sWa[basew + 64] = w.z;
        sWa[basew + 66] = w.w;
    }
    __syncthreads();

    u64 acc2[4][4];
    #pragma unroll
    for (int i = 0; i < 4; i++)
        #pragma unroll
        for (int j = 0; j < 4; j++) acc2[i][j] = 0ull;

    #pragma unroll 2
    for (int dp2 = 0; dp2 < 16; dp2++) {
        ulonglong2 a2[4];
        #pragma unroll
        for (int i = 0; i < 4; i++)
            a2[i] = *(const ulonglong2*)&sA[(rbase + i) * FB_STRIDE + 4 * dp2];
        ulonglong2 wA0 = *(const ulonglong2*)&sWa[(2 * dp2) * 128 + 4 * cg];
        ulonglong2 wA1 = *(const ulonglong2*)&sWa[(2 * dp2) * 128 + 64 + 4 * cg];
        ulonglong2 wB0 = *(const ulonglong2*)&sWa[(2 * dp2 + 1) * 128 + 4 * cg];
        ulonglong2 wB1 = *(const ulonglong2*)&sWa[(2 * dp2 + 1) * 128 + 64 + 4 * cg];
        #pragma unroll
        for (int i = 0; i < 4; i++) {
            ffma2(acc2[i][0], a2[i].x, wA0.x);
            ffma2(acc2[i][1], a2[i].x, wA0.y);
            ffma2(acc2[i][2], a2[i].x, wA1.x);
            ffma2(acc2[i][3], a2[i].x, wA1.y);
            ffma2(acc2[i][0], a2[i].y, wB0.x);
            ffma2(acc2[i][1], a2[i].y, wB0.y);
            ffma2(acc2[i][2], a2[i].y, wB1.x);
            ffma2(acc2[i][3], a2[i].y, wB1.y);
        }
    }
    #pragma unroll
    for (int i = 0; i < 4; i++) {
        int grow = r0 + rbase + i;
        if (grow < N) {
            float4 v;
            v.x = pairsum(acc2[i][0]);
            v.y = pairsum(acc2[i][1]);
            v.z = pairsum(acc2[i][2]);
            v.w = pairsum(acc2[i][3]);
            *(float4*)&g_acc[(size_t)grow * HDIM + 4 * cg] = v;
        }
    }
}

// ---------------------------------------------------------------------------
// kB: STRIDED tiles, grid 1184, 3 CTAs/SM, cp.async double-buffered pipeline.
// smem floats: sWb[2][4096] @0, fb[2][4352] @8192, ints @16896. (unchanged)
// ---------------------------------------------------------------------------
__device__ __forceinline__ void kb_issue(int buf, int k, int t, int cc,
                                         unsigned smem_base, int* sOr, int tid)
{
    int grow_ = tid >> 2;
    int gq = (tid & 3) * 16;
    int orow = -1;
    const float* src = g_f;
    int sz = 0;
    if (grow_ < cc) {
        int2 pr = g_pairs[(size_t)k * NMAX + t * 64 + grow_];
        orow = pr.x;
        src = &g_f[(size_t)pr.y * HDIM + gq];
        sz = 16;
    }
    unsigned fb_addr = smem_base + (8192 + buf * 4352 + grow_ * FB_STRIDE + gq) * 4;
    #pragma unroll
    for (int q = 0; q < 4; q++)
        cp16(fb_addr + q * 16, src + 4 * q, sz);
    if ((tid & 3) == 0) sOr[grow_] = orow;

    const float* wsrc = &g_Wbr[(size_t)k * 4096 + tid * 4];
    unsigned wb_addr = smem_base + (buf * 4096 + tid * 4) * 4;
    #pragma unroll
    for (int q = 0; q < 4; q++)
        cp16(wb_addr + q * 4096, wsrc + q * 1024, 16);
}

__global__ __launch_bounds__(256, 3)
void kb_kernel()
{
    extern __shared__ float sm[];
    int* sPre = (int*)(sm + 16896);        // 64
    int* sCnt = sPre + 64;                 // 64
    int* sOrB0 = sCnt + 64;                // 64
    int* sOrB1 = sOrB0 + 64;               // 64
    unsigned smem_base = (unsigned)__cvta_generic_to_shared(sm);

    int tid = threadIdx.x;
    int wid = tid >> 5, lane = tid & 31;
    int cg = lane & 15, rg = lane >> 4;
    int vb = wid * 8 + rg * 4;

    if (tid < KCONV) sCnt[tid] = g_cnt[tid];
    __syncthreads();
    if (tid == 0) {
        int s = 0;
        for (int k = 0; k < KCONV; k++) {
            sPre[k] = s;
            s += (sCnt[k] + 63) >> 6;
        }
        sPre[KCONV] = s;
    }
    __syncthreads();

    int ntiles = sPre[KCONV];
    int kc = 0;
    int tl = blockIdx.x;
    int b = 0;

    if (tl < ntiles) {
        while (sPre[kc + 1] <= tl) kc++;
        int k = kc, t = tl - sPre[k];
        int cc = min(64, sCnt[k] - t * 64);
        kb_issue(0, k, t, cc, smem_base, sOrB0, tid);
    }
    cp_commit();

    while (tl < ntiles) {
        cp_wait0();
        __syncthreads();   // buffers[b] complete & visible; prev GEMM done

        int tln = tl + gridDim.x;
        if (tln < ntiles) {
            while (sPre[kc + 1] <= tln) kc++;
            int kn = kc, tn = tln - sPre[kn];
            int ccn = min(64, sCnt[kn] - tn * 64);
            kb_issue(1 - b, kn, tn, ccn, smem_base,
                     (1 - b) ? sOrB1 : sOrB0, tid);
        }
        cp_commit();

        const float* fbuf = sm + 8192 + b * 4352;
        const float* sWb  = sm + b * 4096;
        const int*   sOr  = b ? sOrB1 : sOrB0;

        u64 acc[4][4];
        #pragma unroll
        for (int i = 0; i < 4; i++)
            #pragma unroll
            for (int j = 0; j < 4; j++) acc[i][j] = 0ull;

        #pragma unroll 2
        for (int dp2 = 0; dp2 < 16; dp2++) {
            ulonglong2 a2[4];
            #pragma unroll
            for (int i = 0; i < 4; i++)
                a2[i] = *(const ulonglong2*)&fbuf[(vb + i) * FB_STRIDE + 4 * dp2];
            ulonglong2 wA0 = *(const ulonglong2*)&sWb[(2 * dp2) * 128 + 4 * cg];
            ulonglong2 wA1 = *(const ulonglong2*)&sWb[(2 * dp2) * 128 + 64 + 4 * cg];
            ulonglong2 wB0 = *(const ulonglong2*)&sWb[(2 * dp2 + 1) * 128 + 4 * cg];
            ulonglong2 wB1 = *(const ulonglong2*)&sWb[(2 * dp2 + 1) * 128 + 64 + 4 * cg];
            #pragma unroll
            for (int i = 0; i < 4; i++) {
                ffma2(acc[i][0], a2[i].x, wA0.x);
                ffma2(acc[i][1], a2[i].x, wA0.y);
                ffma2(acc[i][2], a2[i].x, wA1.x);
                ffma2(acc[i][3], a2[i].x, wA1.y);
                ffma2(acc[i][0], a2[i].y, wB0.x);
                ffma2(acc[i][1], a2[i].y, wB0.y);
                ffma2(acc[i][2], a2[i].y, wB1.x);
                ffma2(acc[i][3], a2[i].y, wB1.y);
            }
        }
        #pragma unroll
        for (int i = 0; i < 4; i++) {
            int orow = sOr[vb + i];
            if (orow >= 0) {
                red_add_v4(&g_acc[(size_t)orow * HDIM + 4 * cg],
                           pairsum(acc[i][0]), pairsum(acc[i][1]),
                           pairsum(acc[i][2]), pairsum(acc[i][3]));
            }
        }
        tl = tln;
        b ^= 1;
    }
}

// ---------------------------------------------------------------------------
// k3: out = x + elu(g_acc) @ Wc     [N,64]@[64,128]
// 128-row tiles, 3 CTAs/SM. NEW: contiguous-column ownership (lane owns cols
// 4l..4l+3) via c&2-region repack -> single float4 x-load + float4 out-store.
// Wc word: (d>>1)*256 + ((c&2)<<6) + ((c>>2)<<2) + ((c&1)<<1) + (d&1)
//   -> ulonglong2 @ [dp*256 + 4*lane]       = cols {4l, 4l+1}
//   -> ulonglong2 @ [dp*256 + 128 + 4*lane] = cols {4l+2, 4l+3}
// ---------------------------------------------------------------------------
#define HS_STRIDE 68

__global__ __launch_bounds__(256, 3)
void k3_kernel(const float* __restrict__ Wc, const float* __restrict__ x,
               float* __restrict__ out, int N)
{
    extern __shared__ float sm[];
    float* sWc = sm;              // 8192 (region-repacked Wc)
    float* hS  = sm + 8192;       // 128*68 = 8704

    int tid = threadIdx.x;
    int wid = tid >> 5, lane = tid & 31;
    int r0 = blockIdx.x * 128;

    for (int j = tid; j < 2048; j += 256) {
        int d = j >> 5, c0 = (j & 31) * 4;
        float4 w = *(const float4*)&Wc[d * 128 + c0];
        int basew = (d >> 1) * 256 + ((c0 >> 2) << 2) + (d & 1);
        sWc[basew + 0]   = w.x;   // col c0
        sWc[basew + 2]   = w.y;   // col c0+1
        sWc[basew + 128] = w.z;   // col c0+2 (c&2 region)
        sWc[basew + 130] = w.w;   // col c0+3
    }
    for (int j = tid; j < 2048; j += 256) {
        int r = j >> 4, q = (j & 15) * 4;
        int gr = r0 + r;
        float4 v = make_float4(0.f, 0.f, 0.f, 0.f);
        if (gr < N) {
            v = *(const float4*)&g_acc[(size_t)gr * HDIM + q];
            v.x = eluf(v.x); v.y = eluf(v.y);
            v.z = eluf(v.z); v.w = eluf(v.w);
        }
        *(float4*)&hS[r * HS_STRIDE + q] = v;
    }
    __syncthreads();

    #pragma unroll
    for (int half = 0; half < 2; half++) {
        #pragma unroll
        for (int h = 0; h < 2; h++) {
            int rbase = half * 64 + wid * 8 + h * 4;
            u64 acc[4][4];
            #pragma unroll
            for (int i = 0; i < 4; i++)
                #pragma unroll
                for (int j = 0; j < 4; j++) acc[i][j] = 0ull;

            #pragma unroll 2
            for (int dp2 = 0; dp2 < 16; dp2++) {
                ulonglong2 a2[4];
                #pragma unroll
                for (int i = 0; i < 4; i++)
                    a2[i] = *(const ulonglong2*)&hS[(rbase + i) * HS_STRIDE + 4 * dp2];
                ulonglong2 wA0 = *(const ulonglong2*)&sWc[(2 * dp2) * 256 + 4 * lane];
                ulonglong2 wA1 = *(const ulonglong2*)&sWc[(2 * dp2) * 256 + 128 + 4 * lane];
                ulonglong2 wB0 = *(const ulonglong2*)&sWc[(2 * dp2 + 1) * 256 + 4 * lane];
                ulonglong2 wB1 = *(const ulonglong2*)&sWc[(2 * dp2 + 1) * 256 + 128 + 4 * lane];
                #pragma unroll
                for (int i = 0; i < 4; i++) {
                    ffma2(acc[i][0], a2[i].x, wA0.x);   // col 4l
                    ffma2(acc[i][1], a2[i].x, wA0.y);   // col 4l+1
                    ffma2(acc[i][2], a2[i].x, wA1.x);   // col 4l+2
                    ffma2(acc[i][3], a2[i].x, wA1.y);   // col 4l+3
                    ffma2(acc[i][0], a2[i].y, wB0.x);
                    ffma2(acc[i][1], a2[i].y, wB0.y);
                    ffma2(acc[i][2], a2[i].y, wB1.x);
                    ffma2(acc[i][3], a2[i].y, wB1.y);
                }
            }
            #pragma unroll
            for (int i = 0; i < 4; i++) {
                int grow = r0 + rbase + i;
                if (grow < N) {
                    float4 xv = *(const float4*)&x[(size_t)grow * CDIM + 4 * lane];
                    float4 o;
                    o.x = xv.x + pairsum(acc[i][0]);
                    o.y = xv.y + pairsum(acc[i][1]);
                    o.z = xv.z + pairsum(acc[i][2]);
                    o.w = xv.w + pairsum(acc[i][3]);
                    *(float4*)&out[(size_t)grow * CDIM + 4 * lane] = o;
                }
            }
        }
    }
}

// ---------------------------------------------------------------------------
extern "C" void kernel_launch(void* const* d_in, const int* in_sizes, int n_in,
                              void* d_out, int out_size)
{
    const float* x    = (const float*)d_in[0];
    const float* y    = (const float*)d_in[1];
    const float* Wa   = (const float*)d_in[2];
    const float* Wb   = (const float*)d_in[3];
    const float* Wc   = (const float*)d_in[4];
    const int*   nidx = (const int*)  d_in[5];
    float* out = (float*)d_out;

    int N = in_sizes[0] / CDIM;

    const int SMEM1 = (8192 + 64 * SA_STRIDE) * (int)sizeof(float);            // 66560
    const int SMEMB = 16896 * (int)sizeof(float) + 256 * (int)sizeof(int);     // 68608
    const int SMEM3 = (8192 + 128 * HS_STRIDE) * (int)sizeof(float);           // 67584

    cudaFuncSetAttribute(k1_kernel, cudaFuncAttributeMaxDynamicSharedMemorySize, SMEM1);
    cudaFuncSetAttribute(kb_kernel, cudaFuncAttributeMaxDynamicSharedMemorySize, SMEMB);
    cudaFuncSetAttribute(k3_kernel, cudaFuncAttributeMaxDynamicSharedMemorySize, SMEM3);

    int grid1 = (N + 63) / 64;
    int grid3 = (N + 127) / 128;
    int gridA = (N + 511) / 512;

    // launch order: kz, kaA, kaB, k1(#4 -> profiled), kb, k3
    kz_kernel<<<KCONV, 256>>>(Wb);
    ka_kernel<<<dim3(gridA, 31), 512>>>(nidx, N, 0);
    ka_kernel<<<dim3(gridA, 31), 512>>>(nidx, N, 31);
    k1_kernel<<<grid1, 256, SMEM1>>>(x, y, Wa, Wb, N);
    kb_kernel<<<1184, 256, SMEMB>>>();
    k3_kernel<<<grid3, 256, SMEM3>>>(Wc, x, out, N);
}

// round 17
// speedup vs baseline: 1.5565x; 1.5565x over previous
#include <cuda_runtime.h>

#define NMAX   200000
#define HDIM   64
#define CDIM   128
#define KEEPK  63
#define KCONV  62   // offsets handled by kb (center k=62 fused into k1)

// ---- device scratch (static; no allocation) ------------------------------
__device__ __align__(16) float g_f  [(size_t)NMAX * HDIM];   // 51.2 MB
__device__ __align__(16) float g_acc[(size_t)NMAX * HDIM];   // 51.2 MB
__device__ __align__(16) float g_Wbr[(size_t)KCONV * 4096];  // 1 MB repacked Wb
__device__ int2  g_pairs[(size_t)KCONV * NMAX];              // 99.2 MB
__device__ int   g_cnt[KEEPK];

typedef unsigned long long u64;

__device__ __forceinline__ void ffma2(u64 &acc, u64 a, u64 b) {
    asm("fma.rn.f32x2 %0, %1, %2, %0;" : "+l"(acc) : "l"(a), "l"(b));
}
__device__ __forceinline__ float pairsum(u64 v) {
    return __uint_as_float((unsigned)v) + __uint_as_float((unsigned)(v >> 32));
}
__device__ __forceinline__ float eluf(float v) {
    return v > 0.f ? v : __expf(v) - 1.f;
}
__device__ __forceinline__ void red_add_v4(float* p, float a, float b, float c, float d) {
    asm volatile("red.global.add.v4.f32 [%0], {%1, %2, %3, %4};"
                 :: "l"(p), "f"(a), "f"(b), "f"(c), "f"(d) : "memory");
}
__device__ __forceinline__ void cp16(unsigned dst, const void* src, int szbytes) {
    asm volatile("cp.async.cg.shared.global [%0], [%1], 16, %2;"
                 :: "r"(dst), "l"(src), "r"(szbytes) : "memory");
}
__device__ __forceinline__ void cp_commit() {
    asm volatile("cp.async.commit_group;" ::: "memory");
}
__device__ __forceinline__ void cp_wait0() {
    asm volatile("cp.async.wait_group 0;" ::: "memory");
}

// ---------------------------------------------------------------------------
// kZ: zero counters + pre-repack all Wb[k], k<62, into g_Wbr (kb's layout).
// ---------------------------------------------------------------------------
__global__ void kz_kernel(const float* __restrict__ Wb)
{
    int k = blockIdx.x;
    int tid = threadIdx.x;
    if (k == 0 && tid < KEEPK) g_cnt[tid] = 0;
    float* dst = &g_Wbr[(size_t)k * 4096];
    for (int j = tid; j < 1024; j += 256) {
        int dd = j >> 4, c0 = (j & 15) * 4;
        float4 w = *(const float4*)&Wb[(size_t)k * 4096 + dd * 64 + c0];
        int basew = (dd >> 1) * 128 + (c0 >> 2) * 4 + (dd & 1);
        dst[basew + 0]  = w.x;
        dst[basew + 2]  = w.y;
        dst[basew + 64] = w.z;
        dst[basew + 66] = w.w;
    }
}

// ---------------------------------------------------------------------------
// kA: compaction over a half-range [k0, k0+31). 512 threads; block-aggregated
// atomics: ONE atomicAdd per block.
// ---------------------------------------------------------------------------
__global__ void ka_kernel(const int* __restrict__ nidx, int N, int k0)
{
    __shared__ int wcnt[16];
    __shared__ int sbase;
    int k = k0 + blockIdx.y;
    int r = blockIdx.x * blockDim.x + threadIdx.x;
    int idx = -1;
    if (r < N) idx = nidx[(size_t)k * N + r];
    bool valid = idx >= 0;
    unsigned m = __ballot_sync(0xffffffffu, valid);
    int wid = threadIdx.x >> 5, lane = threadIdx.x & 31;
    if (lane == 0) wcnt[wid] = __popc(m);
    __syncthreads();
    if (threadIdx.x == 0) {
        int s = 0;
        #pragma unroll
        for (int w = 0; w < 16; w++) { int c = wcnt[w]; wcnt[w] = s; s += c; }
        sbase = s ? atomicAdd(&g_cnt[k], s) : 0;
    }
    __syncthreads();
    if (valid) {
        int pos = sbase + wcnt[wid] + __popc(m & ((1u << lane) - 1));
        g_pairs[(size_t)k * NMAX + pos] = make_int2(r, idx);
    }
}

// ---------------------------------------------------------------------------
// k1: f = elu( elu(x+y) @ Wa );  g_f = f;  g_acc = f @ Wb[62]  (center fused)
// ---------------------------------------------------------------------------
#define SA_STRIDE 132
#define FB_STRIDE 68

__global__ __launch_bounds__(256, 3)
void k1_kernel(const float* __restrict__ x, const float* __restrict__ y,
               const float* __restrict__ Wa, const float* __restrict__ Wb,
               int N)
{
    extern __shared__ float sm[];
    float* sWa = sm;            // 8192 (pair-major Wa; later reused for Wb62)
    float* sA  = sm + 8192;     // 64*132 = 8448 (input tile; later f tile)

    int tid = threadIdx.x;
    int r0  = blockIdx.x * 64;

    for (int j = tid; j < 2048; j += 256) {
        int d = j >> 4, c0 = (j & 15) * 4;
        float4 w = *(const float4*)&Wa[d * 64 + c0];
        int base = (d >> 1) * 128 + (d & 1);
        sWa[base + 2 * (c0 + 0)] = w.x;
        sWa[base + 2 * (c0 + 1)] = w.y;
        sWa[base + 2 * (c0 + 2)] = w.z;
        sWa[base + 2 * (c0 + 3)] = w.w;
    }
    for (int j = tid; j < 2048; j += 256) {
        int r = j >> 5, c0 = (j & 31) * 4;
        int gr = r0 + r;
        float4 v = make_float4(0.f, 0.f, 0.f, 0.f);
        if (gr < N) {
            float4 xv = *(const float4*)&x[(size_t)gr * CDIM + c0];
            float4 yv = *(const float4*)&y[(size_t)gr * CDIM + c0];
            v.x = eluf(xv.x + yv.x); v.y = eluf(xv.y + yv.y);
            v.z = eluf(xv.z + yv.z); v.w = eluf(xv.w + yv.w);
        }
        *(float4*)&sA[r * SA_STRIDE + c0] = v;
    }
    __syncthreads();

    int wid = tid >> 5, lane = tid & 31;
    int cg = lane & 15, rg = lane >> 4;
    int rbase = wid * 8 + rg * 4;

    u64 acc[4][4];
    #pragma unroll
    for (int i = 0; i < 4; i++)
        #pragma unroll
        for (int j = 0; j < 4; j++) acc[i][j] = 0ull;

    #pragma unroll 2
    for (int dp2 = 0; dp2 < 32; dp2++) {
        ulonglong2 a2[4];
        #pragma unroll
        for (int i = 0; i < 4; i++)
            a2[i] = *(const ulonglong2*)&sA[(rbase + i) * SA_STRIDE + 4 * dp2];
        ulonglong2 wA0 = *(const ulonglong2*)&sWa[(2 * dp2) * 128 + 4 * cg];
        ulonglong2 wA1 = *(const ulonglong2*)&sWa[(2 * dp2) * 128 + 64 + 4 * cg];
        ulonglong2 wB0 = *(const ulonglong2*)&sWa[(2 * dp2 + 1) * 128 + 4 * cg];
        ulonglong2 wB1 = *(const ulonglong2*)&sWa[(2 * dp2 + 1) * 128 + 64 + 4 * cg];
        #pragma unroll
        for (int i = 0; i < 4; i++) {
            ffma2(acc[i][0], a2[i].x, wA0.x);
            ffma2(acc[i][1], a2[i].x, wA0.y);
            ffma2(acc[i][2], a2[i].x, wA1.x);
            ffma2(acc[i][3], a2[i].x, wA1.y);
            ffma2(acc[i][0], a2[i].y, wB0.x);
            ffma2(acc[i][1], a2[i].y, wB0.y);
            ffma2(acc[i][2], a2[i].y, wB1.x);
            ffma2(acc[i][3], a2[i].y, wB1.y);
        }
    }
    float2 f0[4], f1[4];
    #pragma unroll
    for (int i = 0; i < 4; i++) {
        f0[i].x = eluf(pairsum(acc[i][0]));
        f0[i].y = eluf(pairsum(acc[i][1]));
        f1[i].x = eluf(pairsum(acc[i][2]));
        f1[i].y = eluf(pairsum(acc[i][3]));
    }
    __syncthreads();   // all GEMM1 smem reads done; sA/sWa reusable

    #pragma unroll
    for (int i = 0; i < 4; i++) {
        int grow = r0 + rbase + i;
        *(float2*)&sA[(rbase + i) * FB_STRIDE + 2 * cg]      = f0[i];
        *(float2*)&sA[(rbase + i) * FB_STRIDE + 2 * cg + 32] = f1[i];
        if (grow < N) {
            *(float2*)&g_f[(size_t)grow * HDIM + 2 * cg]      = f0[i];
            *(float2*)&g_f[(size_t)grow * HDIM + 2 * cg + 32] = f1[i];
        }
    }
    for (int j = tid; j < 1024; j += 256) {
        int dd = j >> 4, c0 = (j & 15) * 4;
        float4 w = *(const float4*)&Wb[(size_t)KCONV * 4096 + dd * 64 + c0];
        int basew = (dd >> 1) * 128 + (c0 >> 2) * 4 + (dd & 1);
        sWa[basew + 0]  = w.x;
        sWa[basew + 2]  = w.y;
        sWa[basew + 64] = w.z;
        sWa[basew + 66] = w.w;
    }
    __syncthreads();

    u64 acc2[4][4];
    #pragma unroll
    for (int i = 0; i < 4; i++)
        #pragma unroll
        for (int j = 0; j < 4; j++) acc2[i][j] = 0ull;

    #pragma unroll 2
    for (int dp2 = 0; dp2 < 16; dp2++) {
        ulonglong2 a2[4];
        #pragma unroll
        for (int i = 0; i < 4; i++)
            a2[i] = *(const ulonglong2*)&sA[(rbase + i) * FB_STRIDE + 4 * dp2];
        ulonglong2 wA0 = *(const ulonglong2*)&sWa[(2 * dp2) * 128 + 4 * cg];
        ulonglong2 wA1 = *(const ulonglong2*)&sWa[(2 * dp2) * 128 + 64 + 4 * cg];
        ulonglong2 wB0 = *(const ulonglong2*)&sWa[(2 * dp2 + 1) * 128 + 4 * cg];
        ulonglong2 wB1 = *(const ulonglong2*)&sWa[(2 * dp2 + 1) * 128 + 64 + 4 * cg];
        #pragma unroll
        for (int i = 0; i < 4; i++) {
            ffma2(acc2[i][0], a2[i].x, wA0.x);
            ffma2(acc2[i][1], a2[i].x, wA0.y);
            ffma2(acc2[i][2], a2[i].x, wA1.x);
            ffma2(acc2[i][3], a2[i].x, wA1.y);
            ffma2(acc2[i][0], a2[i].y, wB0.x);
            ffma2(acc2[i][1], a2[i].y, wB0.y);
            ffma2(acc2[i][2], a2[i].y, wB1.x);
            ffma2(acc2[i][3], a2[i].y, wB1.y);
        }
    }
    #pragma unroll
    for (int i = 0; i < 4; i++) {
        int grow = r0 + rbase + i;
        if (grow < N) {
            float4 v;
            v.x = pairsum(acc2[i][0]);
            v.y = pairsum(acc2[i][1]);
            v.z = pairsum(acc2[i][2]);
            v.w = pairsum(acc2[i][3]);
            *(float4*)&g_acc[(size_t)grow * HDIM + 4 * cg] = v;
        }
    }
}

// ---------------------------------------------------------------------------
// kB: STRIDED tiles, grid 1184, 3 CTAs/SM, cp.async double-buffered pipeline.
// smem floats: sWb[2][4096] @0, fb[2][4352] @8192, ints @16896.
// ---------------------------------------------------------------------------
__device__ __forceinline__ void kb_issue(int buf, int k, int t, int cc,
                                         unsigned smem_base, int* sOr, int tid)
{
    int grow_ = tid >> 2;
    int gq = (tid & 3) * 16;
    int orow = -1;
    const float* src = g_f;
    int sz = 0;
    if (grow_ < cc) {
        int2 pr = g_pairs[(size_t)k * NMAX + t * 64 + grow_];
        orow = pr.x;
        src = &g_f[(size_t)pr.y * HDIM + gq];
        sz = 16;
    }
    unsigned fb_addr = smem_base + (8192 + buf * 4352 + grow_ * FB_STRIDE + gq) * 4;
    #pragma unroll
    for (int q = 0; q < 4; q++)
        cp16(fb_addr + q * 16, src + 4 * q, sz);
    if ((tid & 3) == 0) sOr[grow_] = orow;

    const float* wsrc = &g_Wbr[(size_t)k * 4096 + tid * 4];
    unsigned wb_addr = smem_base + (buf * 4096 + tid * 4) * 4;
    #pragma unroll
    for (int q = 0; q < 4; q++)
        cp16(wb_addr + q * 4096, wsrc + q * 1024, 16);
}

__global__ __launch_bounds__(256, 3)
void kb_kernel()
{
    extern __shared__ float sm[];
    int* sPre = (int*)(sm + 16896);        // 64
    int* sCnt = sPre + 64;                 // 64
    int* sOrB0 = sCnt + 64;                // 64
    int* sOrB1 = sOrB0 + 64;               // 64
    unsigned smem_base = (unsigned)__cvta_generic_to_shared(sm);

    int tid = threadIdx.x;
    int wid = tid >> 5, lane = tid & 31;
    int cg = lane & 15, rg = lane >> 4;
    int vb = wid * 8 + rg * 4;

    if (tid < KCONV) sCnt[tid] = g_cnt[tid];
    __syncthreads();
    if (tid == 0) {
        int s = 0;
        for (int k = 0; k < KCONV; k++) {
            sPre[k] = s;
            s += (sCnt[k] + 63) >> 6;
        }
        sPre[KCONV] = s;
    }
    __syncthreads();

    int ntiles = sPre[KCONV];
    int kc = 0;
    int tl = blockIdx.x;
    int b = 0;

    if (tl < ntiles) {
        while (sPre[kc + 1] <= tl) kc++;
        int k = kc, t = tl - sPre[k];
        int cc = min(64, sCnt[k] - t * 64);
        kb_issue(0, k, t, cc, smem_base, sOrB0, tid);
    }
    cp_commit();

    while (tl < ntiles) {
        cp_wait0();
        __syncthreads();   // buffers[b] complete & visible; prev GEMM done

        int tln = tl + gridDim.x;
        if (tln < ntiles) {
            while (sPre[kc + 1] <= tln) kc++;
            int kn = kc, tn = tln - sPre[kn];
            int ccn = min(64, sCnt[kn] - tn * 64);
            kb_issue(1 - b, kn, tn, ccn, smem_base,
                     (1 - b) ? sOrB1 : sOrB0, tid);
        }
        cp_commit();

        const float* fbuf = sm + 8192 + b * 4352;
        const float* sWb  = sm + b * 4096;
        const int*   sOr  = b ? sOrB1 : sOrB0;

        u64 acc[4][4];
        #pragma unroll
        for (int i = 0; i < 4; i++)
            #pragma unroll
            for (int j = 0; j < 4; j++) acc[i][j] = 0ull;

        #pragma unroll 2
        for (int dp2 = 0; dp2 < 16; dp2++) {
            ulonglong2 a2[4];
            #pragma unroll
            for (int i = 0; i < 4; i++)
                a2[i] = *(const ulonglong2*)&fbuf[(vb + i) * FB_STRIDE + 4 * dp2];
            ulonglong2 wA0 = *(const ulonglong2*)&sWb[(2 * dp2) * 128 + 4 * cg];
            ulonglong2 wA1 = *(const ulonglong2*)&sWb[(2 * dp2) * 128 + 64 + 4 * cg];
            ulonglong2 wB0 = *(const ulonglong2*)&sWb[(2 * dp2 + 1) * 128 + 4 * cg];
            ulonglong2 wB1 = *(const ulonglong2*)&sWb[(2 * dp2 + 1) * 128 + 64 + 4 * cg];
            #pragma unroll
            for (int i = 0; i < 4; i++) {
                ffma2(acc[i][0], a2[i].x, wA0.x);
                ffma2(acc[i][1], a2[i].x, wA0.y);
                ffma2(acc[i][2], a2[i].x, wA1.x);
                ffma2(acc[i][3], a2[i].x, wA1.y);
                ffma2(acc[i][0], a2[i].y, wB0.x);
                ffma2(acc[i][1], a2[i].y, wB0.y);
                ffma2(acc[i][2], a2[i].y, wB1.x);
                ffma2(acc[i][3], a2[i].y, wB1.y);
            }
        }
        #pragma unroll
        for (int i = 0; i < 4; i++) {
            int orow = sOr[vb + i];
            if (orow >= 0) {
                red_add_v4(&g_acc[(size_t)orow * HDIM + 4 * cg],
                           pairsum(acc[i][0]), pairsum(acc[i][1]),
                           pairsum(acc[i][2]), pairsum(acc[i][3]));
            }
        }
        tl = tln;
        b ^= 1;
    }
}

// ---------------------------------------------------------------------------
// k3: out = x + elu(g_acc) @ Wc     [N,64]@[64,128]
// 128-row tiles, 3 CTAs/SM, contiguous-column ownership (lane owns 4l..4l+3).
// ---------------------------------------------------------------------------
#define HS_STRIDE 68

__global__ __launch_bounds__(256, 3)
void k3_kernel(const float* __restrict__ Wc, const float* __restrict__ x,
               float* __restrict__ out, int N)
{
    extern __shared__ float sm[];
    float* sWc = sm;              // 8192 (region-repacked Wc)
    float* hS  = sm + 8192;       // 128*68 = 8704

    int tid = threadIdx.x;
    int wid = tid >> 5, lane = tid & 31;
    int r0 = blockIdx.x * 128;

    for (int j = tid; j < 2048; j += 256) {
        int d = j >> 5, c0 = (j & 31) * 4;
        float4 w = *(const float4*)&Wc[d * 128 + c0];
        int basew = (d >> 1) * 256 + ((c0 >> 2) << 2) + (d & 1);
        sWc[basew + 0]   = w.x;   // col c0
        sWc[basew + 2]   = w.y;   // col c0+1
        sWc[basew + 128] = w.z;   // col c0+2 (c&2 region)
        sWc[basew + 130] = w.w;   // col c0+3
    }
    for (int j = tid; j < 2048; j += 256) {
        int r = j >> 4, q = (j & 15) * 4;
        int gr = r0 + r;
        float4 v = make_float4(0.f, 0.f, 0.f, 0.f);
        if (gr < N) {
            v = *(const float4*)&g_acc[(size_t)gr * HDIM + q];
            v.x = eluf(v.x); v.y = eluf(v.y);
            v.z = eluf(v.z); v.w = eluf(v.w);
        }
        *(float4*)&hS[r * HS_STRIDE + q] = v;
    }
    __syncthreads();

    #pragma unroll
    for (int half = 0; half < 2; half++) {
        #pragma unroll
        for (int h = 0; h < 2; h++) {
            int rbase = half * 64 + wid * 8 + h * 4;
            u64 acc[4][4];
            #pragma unroll
            for (int i = 0; i < 4; i++)
                #pragma unroll
                for (int j = 0; j < 4; j++) acc[i][j] = 0ull;

            #pragma unroll 2
            for (int dp2 = 0; dp2 < 16; dp2++) {
                ulonglong2 a2[4];
                #pragma unroll
                for (int i = 0; i < 4; i++)
                    a2[i] = *(const ulonglong2*)&hS[(rbase + i) * HS_STRIDE + 4 * dp2];
                ulonglong2 wA0 = *(const ulonglong2*)&sWc[(2 * dp2) * 256 + 4 * lane];
                ulonglong2 wA1 = *(const ulonglong2*)&sWc[(2 * dp2) * 256 + 128 + 4 * lane];
                ulonglong2 wB0 = *(const ulonglong2*)&sWc[(2 * dp2 + 1) * 256 + 4 * lane];
                ulonglong2 wB1 = *(const ulonglong2*)&sWc[(2 * dp2 + 1) * 256 + 128 + 4 * lane];
                #pragma unroll
                for (int i = 0; i < 4; i++) {
                    ffma2(acc[i][0], a2[i].x, wA0.x);   // col 4l
                    ffma2(acc[i][1], a2[i].x, wA0.y);   // col 4l+1
                    ffma2(acc[i][2], a2[i].x, wA1.x);   // col 4l+2
                    ffma2(acc[i][3], a2[i].x, wA1.y);   // col 4l+3
                    ffma2(acc[i][0], a2[i].y, wB0.x);
                    ffma2(acc[i][1], a2[i].y, wB0.y);
                    ffma2(acc[i][2], a2[i].y, wB1.x);
                    ffma2(acc[i][3], a2[i].y, wB1.y);
                }
            }
            #pragma unroll
            for (int i = 0; i < 4; i++) {
                int grow = r0 + rbase + i;
                if (grow < N) {
                    float4 xv = *(const float4*)&x[(size_t)grow * CDIM + 4 * lane];
                    float4 o;
                    o.x = xv.x + pairsum(acc[i][0]);
                    o.y = xv.y + pairsum(acc[i][1]);
                    o.z = xv.z + pairsum(acc[i][2]);
                    o.w = xv.w + pairsum(acc[i][3]);
                    *(float4*)&out[(size_t)grow * CDIM + 4 * lane] = o;
                }
            }
        }
    }
}

// ---------------------------------------------------------------------------
extern "C" void kernel_launch(void* const* d_in, const int* in_sizes, int n_in,
                              void* d_out, int out_size)
{
    const float* x    = (const float*)d_in[0];
    const float* y    = (const float*)d_in[1];
    const float* Wa   = (const float*)d_in[2];
    const float* Wb   = (const float*)d_in[3];
    const float* Wc   = (const float*)d_in[4];
    const int*   nidx = (const int*)  d_in[5];
    float* out = (float*)d_out;

    int N = in_sizes[0] / CDIM;

    const int SMEM1 = (8192 + 64 * SA_STRIDE) * (int)sizeof(float);            // 66560
    const int SMEMB = 16896 * (int)sizeof(float) + 256 * (int)sizeof(int);     // 68608
    const int SMEM3 = (8192 + 128 * HS_STRIDE) * (int)sizeof(float);           // 67584

    cudaFuncSetAttribute(k1_kernel, cudaFuncAttributeMaxDynamicSharedMemorySize, SMEM1);
    cudaFuncSetAttribute(kb_kernel, cudaFuncAttributeMaxDynamicSharedMemorySize, SMEMB);
    cudaFuncSetAttribute(k3_kernel, cudaFuncAttributeMaxDynamicSharedMemorySize, SMEM3);

    int grid1 = (N + 63) / 64;
    int grid3 = (N + 127) / 128;
    int gridA = (N + 511) / 512;

    // launch order: kz, kaA, kaB, k1(#4 -> profiled), kb, k3
    kz_kernel<<<KCONV, 256>>>(Wb);
    ka_kernel<<<dim3(gridA, 31), 512>>>(nidx, N, 0);
    ka_kernel<<<dim3(gridA, 31), 512>>>(nidx, N, 31);
    k1_kernel<<<grid1, 256, SMEM1>>>(x, y, Wa, Wb, N);
    kb_kernel<<<1184, 256, SMEMB>>>();
    k3_kernel<<<grid3, 256, SMEM3>>>(Wc, x, out, N);
}